// round 16
// baseline (speedup 1.0000x reference)
#include <cuda_runtime.h>
#include <cuda_fp16.h>
#include <cstdint>
#include <math.h>

// Problem constants
#define BB 8
#define CC 512
#define NN 4096
#define MM 1024

// Persistent grid: 2 CTAs/SM x 148 SMs
#define PGRID 296

// ---------------------------------------------------------------------------
// Scratch (no cudaMalloc): fp16 operand planes; fp16 expE; fp32 row sums.
// ---------------------------------------------------------------------------
__device__ __half g_Tup16[(size_t)BB * NN * CC];  // pcd_up^T  [B][N][C]
__device__ __half g_Tdn16[(size_t)BB * MM * CC];  // pcd_down^T [B][M][C]
__device__ __half g_Wq16[CC * CC], g_Wk16[CC * CC];
__device__ __half g_Wv16[CC * CC], g_Ws16[CC * CC];
__device__ __half g_Qt16[(size_t)BB * NN * CC];   // Q^T [B][N][C]
__device__ __half g_Kt16[(size_t)BB * MM * CC];   // K^T [B][M][C]
__device__ __half g_V16 [(size_t)BB * CC * MM];   // V [B][C][M]
__device__ __half g_P   [(size_t)BB * NN * MM];   // expE (unnormalized attn)
__device__ float  g_RS  [(size_t)BB * NN];        // row sums of expE

// ---------------------------------------------------------------------------
// helpers
// ---------------------------------------------------------------------------
__device__ __forceinline__ uint32_t smem_u32(const void* p) {
    uint32_t a;
    asm("{ .reg .u64 t; cvta.to.shared.u64 t, %1; cvt.u32.u64 %0, t; }"
        : "=r"(a) : "l"(p));
    return a;
}

__device__ __forceinline__ void mma_f16(float* c, const uint32_t* a,
                                        uint32_t b0, uint32_t b1) {
    asm volatile(
        "mma.sync.aligned.m16n8k16.row.col.f32.f16.f16.f32 "
        "{%0,%1,%2,%3}, {%4,%5,%6,%7}, {%8,%9}, {%0,%1,%2,%3};"
        : "+f"(c[0]), "+f"(c[1]), "+f"(c[2]), "+f"(c[3])
        : "r"(a[0]), "r"(a[1]), "r"(a[2]), "r"(a[3]), "r"(b0), "r"(b1));
}

__device__ __forceinline__ void ldsm4(uint32_t& r0, uint32_t& r1,
                                      uint32_t& r2, uint32_t& r3, uint32_t addr) {
    asm volatile("ldmatrix.sync.aligned.m8n8.x4.shared.b16 {%0,%1,%2,%3}, [%4];"
                 : "=r"(r0), "=r"(r1), "=r"(r2), "=r"(r3) : "r"(addr));
}

#define CP16(dst, src) \
    asm volatile("cp.async.cg.shared.global [%0], [%1], 16;" :: "r"(dst), "l"(src))
#define CP_COMMIT() asm volatile("cp.async.commit_group;" ::: "memory")
#define CP_WAIT1()  asm volatile("cp.async.wait_group 1;" ::: "memory")
#define CP_WAIT0()  asm volatile("cp.async.wait_group 0;" ::: "memory")

// ---------------------------------------------------------------------------
// Merged prologue (single launch):
//  - input transposes: fp32 [C, cols] -> fp16 [cols, C]  (all batches)
//  - weight cvts: Wq, Wk, Wv, Wskip fp32 -> fp16 flat    (z==0 only)
//  - zero RS                                             (z==0 only)
// ---------------------------------------------------------------------------
#define UP_TILES ((NN / 32) * (CC / 32))    // 2048
#define DN_TILES ((MM / 32) * (CC / 32))    // 512
#define IN_TILES (UP_TILES + DN_TILES)      // 2560
#define WCVT_BLK (CC * CC / 256)            // 1024
#define RS_BLK   (BB * NN / 256)            // 128
#define PRO_X    (IN_TILES + 4 * WCVT_BLK + RS_BLK)

__global__ void __launch_bounds__(256) prologue_kernel(
    const float* __restrict__ up, const float* __restrict__ dn,
    const float* __restrict__ Wq, const float* __restrict__ Wk,
    const float* __restrict__ Wv, const float* __restrict__ Ws,
    __half* __restrict__ Tup, __half* __restrict__ Tdn,
    __half* __restrict__ Wq16, __half* __restrict__ Wk16,
    __half* __restrict__ Wv16, __half* __restrict__ Ws16,
    float* __restrict__ RS)
{
    __shared__ float t[32][33];
    int bx = blockIdx.x;
    const int z = blockIdx.z;
    const int tid = threadIdx.x;

    const float* in;
    __half* oh;
    int cols, tile;

    if (bx < IN_TILES) {
        if (bx < UP_TILES) { in = up + (size_t)z * CC * NN; oh = Tup + (size_t)z * CC * NN; cols = NN; tile = bx; }
        else               { in = dn + (size_t)z * CC * MM; oh = Tdn + (size_t)z * CC * MM; cols = MM; tile = bx - UP_TILES; }
    } else {
        if (z != 0) return;
        bx -= IN_TILES;
        if (bx < 4 * WCVT_BLK) {
            const float* W;
            __half* H;
            switch (bx / WCVT_BLK) {
                case 0:  W = Wq; H = Wq16; break;
                case 1:  W = Wk; H = Wk16; break;
                case 2:  W = Wv; H = Wv16; break;
                default: W = Ws; H = Ws16; break;
            }
            int i = (bx % WCVT_BLK) * 256 + tid;
            H[i] = __float2half_rn(W[i]);
        } else {
            int i = (bx - 4 * WCVT_BLK) * 256 + tid;
            RS[i] = 0.0f;
        }
        return;
    }

    const int xt = cols / 32;
    const int c0 = (tile % xt) * 32, r0 = (tile / xt) * 32;
    const int tx = tid & 31, ty = tid >> 5;
    #pragma unroll
    for (int i = 0; i < 32; i += 8)
        t[ty + i][tx] = in[(size_t)(r0 + ty + i) * cols + c0 + tx];
    __syncthreads();
    #pragma unroll
    for (int i = 0; i < 32; i += 8)
        oh[(size_t)(c0 + ty + i) * CC + r0 + tx] = __float2half_rn(t[tx][ty + i]);
}

// ---------------------------------------------------------------------------
// Two-phase GEMM tile body (round-12 proven config).
// outmode: 0 = fp32 store, 2 = fp16 store, 3 = expE + atomic row sums.
// CTA tile 128x128, 256 threads, 8 warps of 32x64, 2 CTAs/SM.
// KT=64; 3-stage cp.async ring (96 KB); one __syncthreads per stage.
// ---------------------------------------------------------------------------
#define KT 64
#define PL 16384                   // 128 rows x 128 B plane
#define STAGEB (2 * PL)            // 32 KB
#define SMEMBYTES (3 * STAGEB)     // 96 KB

__device__ __forceinline__ void gemm_tile2(
    const __half* __restrict__ A1, const __half* __restrict__ B1,
    int lda1, int ldb1, int K1,
    const __half* __restrict__ A2, const __half* __restrict__ B2,
    int lda2, int ldb2, int K2,
    void* __restrict__ Dp, int ldd,
    float scale, int outmode,
    int m0, int n0, char* smem,
    float* __restrict__ rs,
    const float* __restrict__ divrs)
{
    const uint32_t sb = smem_u32(smem);
    const int tid  = threadIdx.x;
    const int wid  = tid >> 5;
    const int lane = tid & 31;
    const int g    = lane >> 2;
    const int t4   = lane & 3;
    const int wm   = (wid >> 1) * 32;
    const int wn   = (wid & 1) * 64;

    float acc[2][8][4] = {};
    const int ns1 = K1 / KT;
    const int nstages = ns1 + K2 / KT;

    auto stage_load = [&](int s, int buf) {
        const __half* A;
        const __half* B;
        int la, lb, k0;
        if (s < ns1) { A = A1; B = B1; la = lda1; lb = ldb1; k0 = s * KT; }
        else         { A = A2; B = B2; la = lda2; lb = ldb2; k0 = (s - ns1) * KT; }
        const uint32_t sbase = sb + buf * STAGEB;
        #pragma unroll
        for (int i = 0; i < 4; i++) {
            int f = tid + i * 256;
            int row = f >> 3, kc = f & 7;
            uint32_t doff = (uint32_t)(row * 128 + ((kc ^ (row & 7)) << 4));
            size_t aoff = (size_t)(m0 + row) * la + k0 + kc * 8;
            size_t boff = (size_t)(n0 + row) * lb + k0 + kc * 8;
            CP16(sbase + doff,      A + aoff);
            CP16(sbase + PL + doff, B + boff);
        }
    };

    auto compute = [&](int buf) {
        const uint32_t bA = sb + buf * STAGEB;
        const uint32_t bB = bA + PL;
        const int t = lane >> 3, ri = lane & 7;
        #pragma unroll
        for (int kp = 0; kp < 4; kp++) {
            uint32_t af[2][4];
            #pragma unroll
            for (int ma = 0; ma < 2; ma++) {
                int row = wm + ma * 16 + (t & 1) * 8 + ri;
                int c   = 2 * kp + (t >> 1);
                uint32_t off = (uint32_t)(row * 128 + ((c ^ (row & 7)) << 4));
                ldsm4(af[ma][0], af[ma][1], af[ma][2], af[ma][3], bA + off);
            }
            #pragma unroll
            for (int np = 0; np < 4; np++) {
                int row = wn + np * 16 + (t >> 1) * 8 + ri;
                int c   = 2 * kp + (t & 1);
                uint32_t off = (uint32_t)(row * 128 + ((c ^ (row & 7)) << 4));
                uint32_t bf[4];
                ldsm4(bf[0], bf[1], bf[2], bf[3], bB + off);
                #pragma unroll
                for (int sub = 0; sub < 2; sub++) {
                    int na = np * 2 + sub;
                    #pragma unroll
                    for (int ma = 0; ma < 2; ma++)
                        mma_f16(acc[ma][na], af[ma], bf[sub * 2], bf[sub * 2 + 1]);
                }
            }
        }
    };

    stage_load(0, 0); CP_COMMIT();
    stage_load(1, 1); CP_COMMIT();

    int buf = 0, nbuf = 2;
    for (int s = 0; s < nstages; s++) {
        if (s + 1 < nstages) CP_WAIT1(); else CP_WAIT0();
        __syncthreads();
        if (s + 2 < nstages) {
            stage_load(s + 2, nbuf);
            CP_COMMIT();
        }
        compute(buf);
        buf = (buf == 2) ? 0 : buf + 1;
        nbuf = (nbuf == 2) ? 0 : nbuf + 1;

        if (divrs && s == ns1 - 1) {
            #pragma unroll
            for (int na = 0; na < 8; na++) {
                const int cb = n0 + wn + na * 8 + 2 * t4;
                float i0 = 1.0f / divrs[cb];
                float i1 = 1.0f / divrs[cb + 1];
                #pragma unroll
                for (int ma = 0; ma < 2; ma++) {
                    acc[ma][na][0] *= i0;
                    acc[ma][na][1] *= i1;
                    acc[ma][na][2] *= i0;
                    acc[ma][na][3] *= i1;
                }
            }
        }
    }

    if (outmode == 3) {
        __half* Dh = (__half*)Dp;
        float rp[2][2] = {{0.f, 0.f}, {0.f, 0.f}};
        #pragma unroll
        for (int ma = 0; ma < 2; ma++) {
            #pragma unroll
            for (int na = 0; na < 8; na++) {
                const int r0 = m0 + wm + ma * 16 + g;
                const int cb = n0 + wn + na * 8 + 2 * t4;
                float v0 = __expf(acc[ma][na][0] * scale);
                float v1 = __expf(acc[ma][na][1] * scale);
                float v2 = __expf(acc[ma][na][2] * scale);
                float v3 = __expf(acc[ma][na][3] * scale);
                __half2 p0; p0.x = __float2half_rn(v0); p0.y = __float2half_rn(v1);
                __half2 p1; p1.x = __float2half_rn(v2); p1.y = __float2half_rn(v3);
                *(__half2*)&Dh[(size_t)r0 * ldd + cb] = p0;
                *(__half2*)&Dh[(size_t)(r0 + 8) * ldd + cb] = p1;
                rp[ma][0] += v0 + v1;
                rp[ma][1] += v2 + v3;
            }
        }
        #pragma unroll
        for (int o = 1; o < 4; o <<= 1) {
            rp[0][0] += __shfl_xor_sync(0xffffffffu, rp[0][0], o);
            rp[0][1] += __shfl_xor_sync(0xffffffffu, rp[0][1], o);
            rp[1][0] += __shfl_xor_sync(0xffffffffu, rp[1][0], o);
            rp[1][1] += __shfl_xor_sync(0xffffffffu, rp[1][1], o);
        }
        if (t4 == 0) {
            #pragma unroll
            for (int ma = 0; ma < 2; ma++)
                #pragma unroll
                for (int h = 0; h < 2; h++)
                    atomicAdd(&rs[m0 + wm + ma * 16 + g + h * 8], rp[ma][h]);
        }
        return;
    }

    #pragma unroll
    for (int ma = 0; ma < 2; ma++) {
        #pragma unroll
        for (int na = 0; na < 8; na++) {
            const int r0 = m0 + wm + ma * 16 + g;
            const int cb = n0 + wn + na * 8 + 2 * t4;
            float v[4] = {acc[ma][na][0] * scale, acc[ma][na][1] * scale,
                          acc[ma][na][2] * scale, acc[ma][na][3] * scale};
            if (outmode == 2) {
                __half* Dh = (__half*)Dp;
                #pragma unroll
                for (int hrow = 0; hrow < 2; hrow++) {
                    size_t o = (size_t)(r0 + hrow * 8) * ldd + cb;
                    __half2 p;
                    p.x = __float2half_rn(v[hrow * 2 + 0]);
                    p.y = __float2half_rn(v[hrow * 2 + 1]);
                    *(__half2*)&Dh[o] = p;
                }
            } else {
                float* D = (float*)Dp;
                #pragma unroll
                for (int hrow = 0; hrow < 2; hrow++)
                    *(float2*)&D[(size_t)(r0 + hrow * 8) * ldd + cb] =
                        make_float2(v[hrow * 2], v[hrow * 2 + 1]);
            }
        }
    }
}

// ---- persistent energy kernel: expE + row sums ----
__global__ void __launch_bounds__(256, 2) tc_gemm_energy(
    const __half* __restrict__ Qt, const __half* __restrict__ Kt,
    __half* __restrict__ P, float* __restrict__ RS, float scale)
{
    extern __shared__ char smem[];
    const int total = BB * (NN / 128) * (MM / 128);   // 2048
    for (int t = blockIdx.x; t < total; t += gridDim.x) {
        const int bz = t >> 8;            // / 256
        const int r  = t & 255;
        const int m0 = (r >> 3) * 128;    // NN tile
        const int n0 = (r & 7) * 128;     // MM tile
        gemm_tile2(Qt + (size_t)bz * NN * CC, Kt + (size_t)bz * MM * CC,
                   CC, CC, CC, nullptr, nullptr, 0, 0, 0,
                   P + (size_t)bz * NN * MM, MM, scale, 3,
                   m0, n0, smem, RS + (size_t)bz * NN, nullptr);
        __syncthreads();   // protect smem ring across tile iterations
    }
}

// ---- persistent fused PV + skip: out = (V·P^T)/rowsum + Wskip·Tup^T ----
__global__ void __launch_bounds__(256, 2) tc_gemm_pv_skip(
    const __half* __restrict__ V,  const __half* __restrict__ P,
    const __half* __restrict__ Ws, const __half* __restrict__ Tup,
    const float* __restrict__ RS, float* __restrict__ out)
{
    extern __shared__ char smem[];
    const int total = BB * (CC / 128) * (NN / 128);   // 1024
    for (int t = blockIdx.x; t < total; t += gridDim.x) {
        const int bz = t >> 7;            // / 128
        const int r  = t & 127;
        const int m0 = (r >> 5) * 128;    // CC tile
        const int n0 = (r & 31) * 128;    // NN tile
        gemm_tile2(V + (size_t)bz * CC * MM, P + (size_t)bz * NN * MM,
                   MM, MM, MM,
                   Ws, Tup + (size_t)bz * NN * CC, CC, CC, CC,
                   out + (size_t)bz * CC * NN, NN, 1.0f, 0,
                   m0, n0, smem, nullptr, RS + (size_t)bz * NN);
        __syncthreads();
    }
}

// ---- persistent merged 3-projection kernel (Qt, Kt, V) ----
struct GDesc {
    const __half* A;
    const __half* B;
    void* D;
    int lda, ldb, ldd;
    size_t strA, strB, strD;
    int ntx;
    int outmode;
};

__global__ void __launch_bounds__(256, 2) tc_gemm_proj(
    GDesc d0, GDesc d1, GDesc d2)
{
    extern __shared__ char smem[];
    const int total = 192 * BB;                        // 1536
    for (int t = blockIdx.x; t < total; t += gridDim.x) {
        const int bz = t / 192;
        int id = t - bz * 192;
        GDesc d;
        if (id < 128)      { d = d0; }
        else if (id < 160) { d = d1; id -= 128; }
        else               { d = d2; id -= 160; }
        const int n0 = (id % d.ntx) * 128;
        const int m0 = (id / d.ntx) * 128;
        gemm_tile2(d.A + (size_t)bz * d.strA, d.B + (size_t)bz * d.strB,
                   d.lda, d.ldb, CC, nullptr, nullptr, 0, 0, 0,
                   (void*)((__half*)d.D + (size_t)bz * d.strD),
                   d.ldd, 1.0f, d.outmode, m0, n0, smem, nullptr, nullptr);
        __syncthreads();
    }
}

// ---------------------------------------------------------------------------
// Launch
// ---------------------------------------------------------------------------
extern "C" void kernel_launch(void* const* d_in, const int* in_sizes, int n_in,
                              void* d_out, int out_size)
{
    const float* pcd_up   = (const float*)d_in[0];
    const float* pcd_down = (const float*)d_in[1];
    const float* Wq       = (const float*)d_in[2];
    const float* Wk       = (const float*)d_in[3];
    const float* Wv       = (const float*)d_in[4];
    const float* Wskip    = (const float*)d_in[5];
    float* out = (float*)d_out;

    __half *Tup, *Tdn, *Wq16, *Wk16, *Wv16, *Ws16, *Qt, *Kt, *V, *P;
    float *RS;
    cudaGetSymbolAddress((void**)&Tup, g_Tup16);
    cudaGetSymbolAddress((void**)&Tdn, g_Tdn16);
    cudaGetSymbolAddress((void**)&Wq16, g_Wq16);
    cudaGetSymbolAddress((void**)&Wk16, g_Wk16);
    cudaGetSymbolAddress((void**)&Wv16, g_Wv16);
    cudaGetSymbolAddress((void**)&Ws16, g_Ws16);
    cudaGetSymbolAddress((void**)&Qt, g_Qt16);
    cudaGetSymbolAddress((void**)&Kt, g_Kt16);
    cudaGetSymbolAddress((void**)&V, g_V16);
    cudaGetSymbolAddress((void**)&P, g_P);
    cudaGetSymbolAddress((void**)&RS, g_RS);

    static bool attr_done = false;
    if (!attr_done) {
        cudaFuncSetAttribute(tc_gemm_energy,
                             cudaFuncAttributeMaxDynamicSharedMemorySize, SMEMBYTES);
        cudaFuncSetAttribute(tc_gemm_proj,
                             cudaFuncAttributeMaxDynamicSharedMemorySize, SMEMBYTES);
        cudaFuncSetAttribute(tc_gemm_pv_skip,
                             cudaFuncAttributeMaxDynamicSharedMemorySize, SMEMBYTES);
        attr_done = true;
    }

    const float rscale = 0.04419417382415922f;  // 1/sqrt(512)
    const size_t sNC = (size_t)NN * CC;
    const size_t sMC = (size_t)MM * CC;

    // 0) merged prologue (single launch): transposes + weight cvts + RS zero
    prologue_kernel<<<dim3(PRO_X, 1, BB), 256>>>(
        pcd_up, pcd_down, Wq, Wk, Wv, Wskip,
        Tup, Tdn, Wq16, Wk16, Wv16, Ws16, RS);

    // 1) Qt/Kt/V projections, persistent (1536 tiles over 296 CTAs)
    GDesc d0 = {Tup,  Wq16, Qt, CC, CC, CC, sNC, 0,   sNC, CC / 128, 2};
    GDesc d1 = {Tdn,  Wk16, Kt, CC, CC, CC, sMC, 0,   sMC, CC / 128, 2};
    GDesc d2 = {Wv16, Tdn,  V,  CC, CC, MM, 0,   sMC, sMC, MM / 128, 2};
    tc_gemm_proj<<<PGRID, 256, SMEMBYTES>>>(d0, d1, d2);

    // 2) expE = exp(rscale * Qt·Kt^T) + row sums, persistent (2048 tiles)
    tc_gemm_energy<<<PGRID, 256, SMEMBYTES>>>(Qt, Kt, P, RS, rscale);

    // 3) out = (V·expE^T)/rowsum + Wskip·Tup^T, persistent (1024 tiles)
    tc_gemm_pv_skip<<<PGRID, 256, SMEMBYTES>>>(V, P, Ws16, Tup, RS, out);
}

// round 17
// speedup vs baseline: 1.1520x; 1.1520x over previous
#include <cuda_runtime.h>
#include <cuda_fp16.h>
#include <cstdint>
#include <math.h>

// Problem constants
#define BB 8
#define CC 512
#define NN 4096
#define MM 1024

// ---------------------------------------------------------------------------
// Scratch (no cudaMalloc)
// ---------------------------------------------------------------------------
__device__ __half g_Tup16[(size_t)BB * NN * CC];  // pcd_up^T  [B][N][C]
__device__ __half g_Tdn16[(size_t)BB * MM * CC];  // pcd_down^T [B][M][C]
__device__ __half g_WqT[CC * CC];                 // Wq^T [c][i]
__device__ __half g_WkT[CC * CC];                 // Wk^T [c][i]
__device__ __half g_Wv16[CC * CC], g_Ws16[CC * CC];
__device__ __half g_G  [CC * CC];                 // G[c][c'] = sum_i Wq[i,c]Wk[i,c']
__device__ __half g_Kg [(size_t)BB * MM * CC];    // Kg[m][c] = sum_c' Tdn[m,c']G[c,c']
__device__ __half g_V16[(size_t)BB * CC * MM];    // V [B][C][M]
__device__ __half g_P  [(size_t)BB * NN * MM];    // expE (unnormalized attn)
__device__ float  g_RS [(size_t)BB * NN];         // row sums of expE

// ---------------------------------------------------------------------------
// helpers
// ---------------------------------------------------------------------------
__device__ __forceinline__ uint32_t smem_u32(const void* p) {
    uint32_t a;
    asm("{ .reg .u64 t; cvta.to.shared.u64 t, %1; cvt.u32.u64 %0, t; }"
        : "=r"(a) : "l"(p));
    return a;
}

__device__ __forceinline__ void mma_f16(float* c, const uint32_t* a,
                                        uint32_t b0, uint32_t b1) {
    asm volatile(
        "mma.sync.aligned.m16n8k16.row.col.f32.f16.f16.f32 "
        "{%0,%1,%2,%3}, {%4,%5,%6,%7}, {%8,%9}, {%0,%1,%2,%3};"
        : "+f"(c[0]), "+f"(c[1]), "+f"(c[2]), "+f"(c[3])
        : "r"(a[0]), "r"(a[1]), "r"(a[2]), "r"(a[3]), "r"(b0), "r"(b1));
}

__device__ __forceinline__ void ldsm4(uint32_t& r0, uint32_t& r1,
                                      uint32_t& r2, uint32_t& r3, uint32_t addr) {
    asm volatile("ldmatrix.sync.aligned.m8n8.x4.shared.b16 {%0,%1,%2,%3}, [%4];"
                 : "=r"(r0), "=r"(r1), "=r"(r2), "=r"(r3) : "r"(addr));
}

#define CP16(dst, src) \
    asm volatile("cp.async.cg.shared.global [%0], [%1], 16;" :: "r"(dst), "l"(src))
#define CP_COMMIT() asm volatile("cp.async.commit_group;" ::: "memory")
#define CP_WAIT1()  asm volatile("cp.async.wait_group 1;" ::: "memory")
#define CP_WAIT0()  asm volatile("cp.async.wait_group 0;" ::: "memory")

// ---------------------------------------------------------------------------
// Merged prologue:
//  - input transposes: fp32 [C, cols] -> fp16 [cols, C]  (all batches)
//  - weight transposes: Wq,Wk fp32 [i][c] -> WqT,WkT fp16 [c][i]   (z==0)
//  - weight cvts: Wv, Wskip fp32 -> fp16 flat                      (z==0)
//  - zero RS                                                       (z==0)
// ---------------------------------------------------------------------------
#define UP_TILES ((NN / 32) * (CC / 32))    // 2048
#define DN_TILES ((MM / 32) * (CC / 32))    // 512
#define IN_TILES (UP_TILES + DN_TILES)      // 2560
#define WT_TILES ((CC / 32) * (CC / 32))    // 256
#define WCVT_BLK (CC * CC / 256)            // 1024
#define RS_BLK   (BB * NN / 256)            // 128
#define PRO_X    (IN_TILES + 2 * WT_TILES + 2 * WCVT_BLK + RS_BLK)

__global__ void __launch_bounds__(256) prologue_kernel(
    const float* __restrict__ up, const float* __restrict__ dn,
    const float* __restrict__ Wq, const float* __restrict__ Wk,
    const float* __restrict__ Wv, const float* __restrict__ Ws,
    __half* __restrict__ Tup, __half* __restrict__ Tdn,
    __half* __restrict__ WqT, __half* __restrict__ WkT,
    __half* __restrict__ Wv16, __half* __restrict__ Ws16,
    float* __restrict__ RS)
{
    __shared__ float t[32][33];
    int bx = blockIdx.x;
    const int z = blockIdx.z;
    const int tid = threadIdx.x;

    const float* in = nullptr;
    __half* oh = nullptr;
    int cols = 0, tile = 0;

    if (bx < IN_TILES) {
        if (bx < UP_TILES) { in = up + (size_t)z * CC * NN; oh = Tup + (size_t)z * CC * NN; cols = NN; tile = bx; }
        else               { in = dn + (size_t)z * CC * MM; oh = Tdn + (size_t)z * CC * MM; cols = MM; tile = bx - UP_TILES; }
    } else {
        if (z != 0) return;
        bx -= IN_TILES;
        if (bx < WT_TILES)              { in = Wq; oh = WqT; cols = CC; tile = bx; }
        else if (bx < 2 * WT_TILES)     { in = Wk; oh = WkT; cols = CC; tile = bx - WT_TILES; }
        else {
            bx -= 2 * WT_TILES;
            if (bx < 2 * WCVT_BLK) {
                const float* W = (bx < WCVT_BLK) ? Wv : Ws;
                __half* H = (bx < WCVT_BLK) ? Wv16 : Ws16;
                int i = (bx % WCVT_BLK) * 256 + tid;
                H[i] = __float2half_rn(W[i]);
            } else {
                int i = (bx - 2 * WCVT_BLK) * 256 + tid;
                RS[i] = 0.0f;
            }
            return;
        }
    }

    const int xt = cols / 32;
    const int c0 = (tile % xt) * 32, r0 = (tile / xt) * 32;
    const int tx = tid & 31, ty = tid >> 5;
    #pragma unroll
    for (int i = 0; i < 32; i += 8)
        t[ty + i][tx] = in[(size_t)(r0 + ty + i) * cols + c0 + tx];
    __syncthreads();
    #pragma unroll
    for (int i = 0; i < 32; i += 8)
        oh[(size_t)(c0 + ty + i) * CC + r0 + tx] = __float2half_rn(t[tx][ty + i]);
}

// ---------------------------------------------------------------------------
// Two-phase GEMM tile body (round-12 proven config).
// outmode: 0 = fp32 store, 2 = fp16 store, 3 = expE + atomic row sums.
// CTA tile 128x128, 256 threads, 8 warps of 32x64, 2 CTAs/SM.
// KT=64; 3-stage cp.async ring (96 KB); one __syncthreads per stage.
// ---------------------------------------------------------------------------
#define KT 64
#define PL 16384                   // 128 rows x 128 B plane
#define STAGEB (2 * PL)            // 32 KB
#define SMEMBYTES (3 * STAGEB)     // 96 KB

__device__ __forceinline__ void gemm_tile2(
    const __half* __restrict__ A1, const __half* __restrict__ B1,
    int lda1, int ldb1, int K1,
    const __half* __restrict__ A2, const __half* __restrict__ B2,
    int lda2, int ldb2, int K2,
    void* __restrict__ Dp, int ldd,
    float scale, int outmode,
    int m0, int n0, char* smem,
    float* __restrict__ rs,
    const float* __restrict__ divrs)
{
    const uint32_t sb = smem_u32(smem);
    const int tid  = threadIdx.x;
    const int wid  = tid >> 5;
    const int lane = tid & 31;
    const int g    = lane >> 2;
    const int t4   = lane & 3;
    const int wm   = (wid >> 1) * 32;
    const int wn   = (wid & 1) * 64;

    float acc[2][8][4] = {};
    const int ns1 = K1 / KT;
    const int nstages = ns1 + K2 / KT;

    auto stage_load = [&](int s, int buf) {
        const __half* A;
        const __half* B;
        int la, lb, k0;
        if (s < ns1) { A = A1; B = B1; la = lda1; lb = ldb1; k0 = s * KT; }
        else         { A = A2; B = B2; la = lda2; lb = ldb2; k0 = (s - ns1) * KT; }
        const uint32_t sbase = sb + buf * STAGEB;
        #pragma unroll
        for (int i = 0; i < 4; i++) {
            int f = tid + i * 256;
            int row = f >> 3, kc = f & 7;
            uint32_t doff = (uint32_t)(row * 128 + ((kc ^ (row & 7)) << 4));
            size_t aoff = (size_t)(m0 + row) * la + k0 + kc * 8;
            size_t boff = (size_t)(n0 + row) * lb + k0 + kc * 8;
            CP16(sbase + doff,      A + aoff);
            CP16(sbase + PL + doff, B + boff);
        }
    };

    auto compute = [&](int buf) {
        const uint32_t bA = sb + buf * STAGEB;
        const uint32_t bB = bA + PL;
        const int t = lane >> 3, ri = lane & 7;
        #pragma unroll
        for (int kp = 0; kp < 4; kp++) {
            uint32_t af[2][4];
            #pragma unroll
            for (int ma = 0; ma < 2; ma++) {
                int row = wm + ma * 16 + (t & 1) * 8 + ri;
                int c   = 2 * kp + (t >> 1);
                uint32_t off = (uint32_t)(row * 128 + ((c ^ (row & 7)) << 4));
                ldsm4(af[ma][0], af[ma][1], af[ma][2], af[ma][3], bA + off);
            }
            #pragma unroll
            for (int np = 0; np < 4; np++) {
                int row = wn + np * 16 + (t >> 1) * 8 + ri;
                int c   = 2 * kp + (t & 1);
                uint32_t off = (uint32_t)(row * 128 + ((c ^ (row & 7)) << 4));
                uint32_t bf[4];
                ldsm4(bf[0], bf[1], bf[2], bf[3], bB + off);
                #pragma unroll
                for (int sub = 0; sub < 2; sub++) {
                    int na = np * 2 + sub;
                    #pragma unroll
                    for (int ma = 0; ma < 2; ma++)
                        mma_f16(acc[ma][na], af[ma], bf[sub * 2], bf[sub * 2 + 1]);
                }
            }
        }
    };

    stage_load(0, 0); CP_COMMIT();
    stage_load(1, 1); CP_COMMIT();

    int buf = 0, nbuf = 2;
    for (int s = 0; s < nstages; s++) {
        if (s + 1 < nstages) CP_WAIT1(); else CP_WAIT0();
        __syncthreads();
        if (s + 2 < nstages) {
            stage_load(s + 2, nbuf);
            CP_COMMIT();
        }
        compute(buf);
        buf = (buf == 2) ? 0 : buf + 1;
        nbuf = (nbuf == 2) ? 0 : nbuf + 1;

        if (divrs && s == ns1 - 1) {
            #pragma unroll
            for (int na = 0; na < 8; na++) {
                const int cb = n0 + wn + na * 8 + 2 * t4;
                float i0 = 1.0f / divrs[cb];
                float i1 = 1.0f / divrs[cb + 1];
                #pragma unroll
                for (int ma = 0; ma < 2; ma++) {
                    acc[ma][na][0] *= i0;
                    acc[ma][na][1] *= i1;
                    acc[ma][na][2] *= i0;
                    acc[ma][na][3] *= i1;
                }
            }
        }
    }

    if (outmode == 3) {
        __half* Dh = (__half*)Dp;
        float rp[2][2] = {{0.f, 0.f}, {0.f, 0.f}};
        #pragma unroll
        for (int ma = 0; ma < 2; ma++) {
            #pragma unroll
            for (int na = 0; na < 8; na++) {
                const int r0 = m0 + wm + ma * 16 + g;
                const int cb = n0 + wn + na * 8 + 2 * t4;
                float v0 = __expf(acc[ma][na][0] * scale);
                float v1 = __expf(acc[ma][na][1] * scale);
                float v2 = __expf(acc[ma][na][2] * scale);
                float v3 = __expf(acc[ma][na][3] * scale);
                __half2 p0; p0.x = __float2half_rn(v0); p0.y = __float2half_rn(v1);
                __half2 p1; p1.x = __float2half_rn(v2); p1.y = __float2half_rn(v3);
                *(__half2*)&Dh[(size_t)r0 * ldd + cb] = p0;
                *(__half2*)&Dh[(size_t)(r0 + 8) * ldd + cb] = p1;
                rp[ma][0] += v0 + v1;
                rp[ma][1] += v2 + v3;
            }
        }
        #pragma unroll
        for (int o = 1; o < 4; o <<= 1) {
            rp[0][0] += __shfl_xor_sync(0xffffffffu, rp[0][0], o);
            rp[0][1] += __shfl_xor_sync(0xffffffffu, rp[0][1], o);
            rp[1][0] += __shfl_xor_sync(0xffffffffu, rp[1][0], o);
            rp[1][1] += __shfl_xor_sync(0xffffffffu, rp[1][1], o);
        }
        if (t4 == 0) {
            #pragma unroll
            for (int ma = 0; ma < 2; ma++)
                #pragma unroll
                for (int h = 0; h < 2; h++)
                    atomicAdd(&rs[m0 + wm + ma * 16 + g + h * 8], rp[ma][h]);
        }
        return;
    }

    #pragma unroll
    for (int ma = 0; ma < 2; ma++) {
        #pragma unroll
        for (int na = 0; na < 8; na++) {
            const int r0 = m0 + wm + ma * 16 + g;
            const int cb = n0 + wn + na * 8 + 2 * t4;
            float v[4] = {acc[ma][na][0] * scale, acc[ma][na][1] * scale,
                          acc[ma][na][2] * scale, acc[ma][na][3] * scale};
            if (outmode == 2) {
                __half* Dh = (__half*)Dp;
                #pragma unroll
                for (int hrow = 0; hrow < 2; hrow++) {
                    size_t o = (size_t)(r0 + hrow * 8) * ldd + cb;
                    __half2 p;
                    p.x = __float2half_rn(v[hrow * 2 + 0]);
                    p.y = __float2half_rn(v[hrow * 2 + 1]);
                    *(__half2*)&Dh[o] = p;
                }
            } else {
                float* D = (float*)Dp;
                #pragma unroll
                for (int hrow = 0; hrow < 2; hrow++)
                    *(float2*)&D[(size_t)(r0 + hrow * 8) * ldd + cb] =
                        make_float2(v[hrow * 2], v[hrow * 2 + 1]);
            }
        }
    }
}

// ---- Gram matrix: G[c][c'] = sum_i WqT[c][i] WkT[c'][i]  (grid 4x4) ----
__global__ void __launch_bounds__(256, 2) tc_gemm_g(
    const __half* __restrict__ WqT, const __half* __restrict__ WkT,
    __half* __restrict__ G)
{
    extern __shared__ char smem[];
    gemm_tile2(WqT, WkT, CC, CC, CC, nullptr, nullptr, 0, 0, 0,
               G, CC, 1.0f, 2, blockIdx.y * 128, blockIdx.x * 128, smem,
               nullptr, nullptr);
}

// ---- energy: expE[n][m] = exp(rscale * Tup·Kg^T) + atomic row sums ----
__global__ void __launch_bounds__(256, 2) tc_gemm_energy(
    const __half* __restrict__ Tup, const __half* __restrict__ Kg,
    __half* __restrict__ P, float* __restrict__ RS, float scale)
{
    extern __shared__ char smem[];
    const int bz = blockIdx.z;
    gemm_tile2(Tup + (size_t)bz * NN * CC, Kg + (size_t)bz * MM * CC,
               CC, CC, CC, nullptr, nullptr, 0, 0, 0,
               P + (size_t)bz * NN * MM, MM, scale, 3,
               blockIdx.y * 128, blockIdx.x * 128, smem,
               RS + (size_t)bz * NN, nullptr);
}

// ---- fused PV + skip: out = (V·P^T)/rowsum + Wskip·Tup^T ----
__global__ void __launch_bounds__(256, 2) tc_gemm_pv_skip(
    const __half* __restrict__ V,  const __half* __restrict__ P,
    const __half* __restrict__ Ws, const __half* __restrict__ Tup,
    const float* __restrict__ RS, float* __restrict__ out)
{
    extern __shared__ char smem[];
    const int bz = blockIdx.z;
    gemm_tile2(V + (size_t)bz * CC * MM, P + (size_t)bz * NN * MM,
               MM, MM, MM,
               Ws, Tup + (size_t)bz * NN * CC, CC, CC, CC,
               out + (size_t)bz * CC * NN, NN, 1.0f, 0,
               blockIdx.y * 128, blockIdx.x * 128, smem,
               nullptr, RS + (size_t)bz * NN);
}

// ---- merged projection kernel (Kg, V): 64 tiles/batch ----
struct GDesc {
    const __half* A;
    const __half* B;
    void* D;
    int lda, ldb, ldd;
    size_t strA, strB, strD;
    int ntx;
    int outmode;
};

__global__ void __launch_bounds__(256, 2) tc_gemm_proj(GDesc d0, GDesc d1)
{
    extern __shared__ char smem[];
    int id = blockIdx.x;
    GDesc d;
    if (id < 32) { d = d0; }
    else         { d = d1; id -= 32; }
    const int bz = blockIdx.z;
    const int n0 = (id % d.ntx) * 128;
    const int m0 = (id / d.ntx) * 128;
    gemm_tile2(d.A + (size_t)bz * d.strA, d.B + (size_t)bz * d.strB,
               d.lda, d.ldb, CC, nullptr, nullptr, 0, 0, 0,
               (void*)((__half*)d.D + (size_t)bz * d.strD),
               d.ldd, 1.0f, d.outmode, m0, n0, smem, nullptr, nullptr);
}

// ---------------------------------------------------------------------------
// Launch
// ---------------------------------------------------------------------------
extern "C" void kernel_launch(void* const* d_in, const int* in_sizes, int n_in,
                              void* d_out, int out_size)
{
    const float* pcd_up   = (const float*)d_in[0];
    const float* pcd_down = (const float*)d_in[1];
    const float* Wq       = (const float*)d_in[2];
    const float* Wk       = (const float*)d_in[3];
    const float* Wv       = (const float*)d_in[4];
    const float* Wskip    = (const float*)d_in[5];
    float* out = (float*)d_out;

    __half *Tup, *Tdn, *WqT, *WkT, *Wv16, *Ws16, *G, *Kg, *V, *P;
    float *RS;
    cudaGetSymbolAddress((void**)&Tup, g_Tup16);
    cudaGetSymbolAddress((void**)&Tdn, g_Tdn16);
    cudaGetSymbolAddress((void**)&WqT, g_WqT);
    cudaGetSymbolAddress((void**)&WkT, g_WkT);
    cudaGetSymbolAddress((void**)&Wv16, g_Wv16);
    cudaGetSymbolAddress((void**)&Ws16, g_Ws16);
    cudaGetSymbolAddress((void**)&G, g_G);
    cudaGetSymbolAddress((void**)&Kg, g_Kg);
    cudaGetSymbolAddress((void**)&V, g_V16);
    cudaGetSymbolAddress((void**)&P, g_P);
    cudaGetSymbolAddress((void**)&RS, g_RS);

    static bool attr_done = false;
    if (!attr_done) {
        cudaFuncSetAttribute(tc_gemm_g,
                             cudaFuncAttributeMaxDynamicSharedMemorySize, SMEMBYTES);
        cudaFuncSetAttribute(tc_gemm_energy,
                             cudaFuncAttributeMaxDynamicSharedMemorySize, SMEMBYTES);
        cudaFuncSetAttribute(tc_gemm_proj,
                             cudaFuncAttributeMaxDynamicSharedMemorySize, SMEMBYTES);
        cudaFuncSetAttribute(tc_gemm_pv_skip,
                             cudaFuncAttributeMaxDynamicSharedMemorySize, SMEMBYTES);
        attr_done = true;
    }

    const float rscale = 0.04419417382415922f;  // 1/sqrt(512)
    const size_t sNC = (size_t)NN * CC;
    const size_t sMC = (size_t)MM * CC;

    // 0) merged prologue: input transposes, WqT/WkT, Wv/Ws cvt, RS zero
    prologue_kernel<<<dim3(PRO_X, 1, BB), 256>>>(
        pcd_up, pcd_down, Wq, Wk, Wv, Wskip,
        Tup, Tdn, WqT, WkT, Wv16, Ws16, RS);

    // 1) G[c][c'] = sum_i Wq[i,c] Wk[i,c']  (16 CTAs)
    tc_gemm_g<<<dim3(4, 4, 1), 256, SMEMBYTES>>>(WqT, WkT, G);

    // 2) Kg[m][c] = sum_c' Tdn[m,c'] G[c,c']  (32 tiles/batch)
    //    V[o][m]  = sum_c Wv[o,c] Tdn[m,c]    (32 tiles/batch)
    GDesc d0 = {Tdn,  G,   Kg, CC, CC, CC, sMC, 0,   sMC, CC / 128, 2};
    GDesc d1 = {Wv16, Tdn, V,  CC, CC, MM, 0,   sMC, sMC, MM / 128, 2};
    tc_gemm_proj<<<dim3(64, 1, BB), 256, SMEMBYTES>>>(d0, d1);

    // 3) expE[n][m] = exp(rscale * Tup·Kg^T); row sums atomically
    tc_gemm_energy<<<dim3(MM / 128, NN / 128, BB), 256, SMEMBYTES>>>(
        Tup, Kg, P, RS, rscale);

    // 4) out[c][n] = (V·expE^T)/rowsum[n] + Wskip·Tup^T
    tc_gemm_pv_skip<<<dim3(NN / 128, CC / 128, BB), 256, SMEMBYTES>>>(
        V, P, Ws16, Tup, RS, out);
}